// round 8
// baseline (speedup 1.0000x reference)
#include <cuda_runtime.h>
#include <cstdint>

#define UNITS   2048
#define IN_DIM  512
#define TSTEPS  8192
#define NCTA    128
#define SCAN_THREADS 256

// 64 MB staging buffer for xin = x @ wax^T + ba
__device__ float g_xin[(size_t)TSTEPS * UNITS];
// double-buffered state publication: word = {val:hi32, stamp:lo32}
// slot s&1 holds a_s with stamp s+1
__device__ unsigned long long g_pub[2][UNITS];

__device__ __forceinline__ unsigned long long ld_relaxed_u64(
    const unsigned long long* p) {
    unsigned long long v;
    asm volatile("ld.relaxed.gpu.global.u64 %0, [%1];" : "=l"(v) : "l"(p) : "memory");
    return v;
}
__device__ __forceinline__ void st_relaxed_u64(unsigned long long* p,
                                               unsigned long long v) {
    asm volatile("st.relaxed.gpu.global.u64 [%0], %1;" :: "l"(p), "l"(v) : "memory");
}
__device__ __forceinline__ unsigned long long ffma2(
    unsigned long long a, unsigned long long b, unsigned long long c) {
    unsigned long long d;
    asm("fma.rn.f32x2 %0, %1, %2, %3;" : "=l"(d) : "l"(a), "l"(b), "l"(c));
    return d;
}
__device__ __forceinline__ unsigned long long packf2(float x, float y) {
    unsigned long long p;
    asm("mov.b64 %0, {%1, %2};" : "=l"(p) : "f"(x), "f"(y));
    return p;
}
__device__ __forceinline__ float pair_sum(unsigned long long p) {
    float lo, hi;
    asm("mov.b64 {%0, %1}, %2;" : "=f"(lo), "=f"(hi) : "l"(p));
    return lo + hi;
}
__device__ __forceinline__ float pub_val(unsigned long long w) {
    return __uint_as_float((unsigned)(w >> 32));
}
__device__ __forceinline__ unsigned long long make_pub(float v, unsigned stamp) {
    return ((unsigned long long)__float_as_uint(v) << 32) | (unsigned long long)stamp;
}

// ---------------------------------------------------------------------------
// Phase 1: xin[t][u] = sum_d x[t][d] * wax[u][d] + ba[u]
// blockIdx.y==0 blocks also zero the publication stamps (every replay).
// ---------------------------------------------------------------------------
__global__ __launch_bounds__(256) void xin_gemm_kernel(
    const float* __restrict__ x,     // [8192][512]
    const float* __restrict__ wax,   // [2048][512]
    const float* __restrict__ ba)    // [2048]
{
    if (blockIdx.y == 0) {
        int idx = blockIdx.x * 256 + threadIdx.x;   // 32*256 = 8192 >= 4096
        if (idx < 2 * UNITS)
            ((unsigned long long*)g_pub)[idx] = 0ull;
    }

    __shared__ float As[16][128 + 4];
    __shared__ float Bs[16][64 + 4];

    const int tid = threadIdx.x;
    const int bm = blockIdx.y * 128;
    const int bn = blockIdx.x * 64;
    const int tx = tid & 15;
    const int ty = tid >> 4;

    float acc[8][4];
#pragma unroll
    for (int i = 0; i < 8; i++)
#pragma unroll
        for (int j = 0; j < 4; j++) acc[i][j] = 0.f;

    const int lr = tid >> 2;
    const int lc = (tid & 3) * 4;

    for (int k0 = 0; k0 < IN_DIM; k0 += 16) {
        float4 a0 = *(const float4*)&x[(size_t)(bm + lr) * IN_DIM + k0 + lc];
        float4 a1 = *(const float4*)&x[(size_t)(bm + lr + 64) * IN_DIM + k0 + lc];
        float4 b0 = *(const float4*)&wax[(size_t)(bn + lr) * IN_DIM + k0 + lc];

        As[lc + 0][lr] = a0.x; As[lc + 1][lr] = a0.y;
        As[lc + 2][lr] = a0.z; As[lc + 3][lr] = a0.w;
        As[lc + 0][lr + 64] = a1.x; As[lc + 1][lr + 64] = a1.y;
        As[lc + 2][lr + 64] = a1.z; As[lc + 3][lr + 64] = a1.w;
        Bs[lc + 0][lr] = b0.x; Bs[lc + 1][lr] = b0.y;
        Bs[lc + 2][lr] = b0.z; Bs[lc + 3][lr] = b0.w;
        __syncthreads();

#pragma unroll
        for (int kk = 0; kk < 16; kk++) {
            float4 av0 = *(const float4*)&As[kk][ty * 8];
            float4 av1 = *(const float4*)&As[kk][ty * 8 + 4];
            float4 bv  = *(const float4*)&Bs[kk][tx * 4];
            float a[8] = {av0.x, av0.y, av0.z, av0.w, av1.x, av1.y, av1.z, av1.w};
            float b[4] = {bv.x, bv.y, bv.z, bv.w};
#pragma unroll
            for (int i = 0; i < 8; i++)
#pragma unroll
                for (int j = 0; j < 4; j++)
                    acc[i][j] = fmaf(a[i], b[j], acc[i][j]);
        }
        __syncthreads();
    }

    float4 bav = *(const float4*)&ba[bn + tx * 4];
#pragma unroll
    for (int i = 0; i < 8; i++) {
        float4 c;
        c.x = acc[i][0] + bav.x;
        c.y = acc[i][1] + bav.y;
        c.z = acc[i][2] + bav.z;
        c.w = acc[i][3] + bav.w;
        *(float4*)&g_xin[(size_t)(bm + ty * 8 + i) * UNITS + bn + tx * 4] = c;
    }
}

// ---------------------------------------------------------------------------
// Phase 2: persistent scan with stamped data publication.
// 128 CTAs x 256 threads; CTA owns 16 rows, warp w owns rows {16c+2w, +1};
// lane holds cols {128k+4l..+3} for both rows (f32x2 packed, 128 regs).
// Per step t>0:
//   each thread polls its 8 state words (2x 32B groups) from slot (t-1)&1
//   until all stamps == t  (the poll IS the data load; word atomicity
//   makes val+stamp consistent; no fences anywhere)
//   -> stage values to SMEM -> __syncthreads -> 64 FFMA2 -> 10-shfl
//   butterfly -> lane0: tanh, store out[t], publish 2 stamped words to
//   slot t&1 with stamp t+1 -> __syncthreads (protects a_sm reuse).
// Double buffering is safe: a CTA publishes a_{t+1} only after seeing all
// stamps t+1, which implies every CTA finished reading a_{t-1}.
// ---------------------------------------------------------------------------
__global__ __launch_bounds__(SCAN_THREADS, 1) void scan_kernel(
    const float* __restrict__ waa,   // [2048][2048]
    float* __restrict__ out)         // [8192][2048]
{
    __shared__ float a_sm[UNITS];
    float4* a_sm4 = (float4*)a_sm;

    const int tid  = threadIdx.x;
    const int lane = tid & 31;
    const int warp = tid >> 5;               // 0..7
    const int cta  = blockIdx.x;             // 0..127
    const int row0 = cta * 16 + warp * 2;

    // Preload weights packed as f32x2
    unsigned long long w0[16][2], w1[16][2];
#pragma unroll
    for (int k = 0; k < 16; k++) {
        float4 f0 = *(const float4*)&waa[(size_t)row0 * UNITS + k * 128 + lane * 4];
        float4 f1 = *(const float4*)&waa[(size_t)(row0 + 1) * UNITS + k * 128 + lane * 4];
        w0[k][0] = packf2(f0.x, f0.y); w0[k][1] = packf2(f0.z, f0.w);
        w1[k][0] = packf2(f1.x, f1.y); w1[k][1] = packf2(f1.z, f1.w);
    }

    for (int t = 0; t < TSTEPS; t++) {
        float2 xv;
        if (lane == 0)
            xv = *(const float2*)&g_xin[(size_t)t * UNITS + row0];

        if (t > 0) {
            const unsigned long long* src = g_pub[(t - 1) & 1];
            const unsigned long long* s0p = src + 4 * tid;          // elems 4t..+3
            const unsigned long long* s1p = src + 1024 + 4 * tid;   // elems 1024+4t..+3
            const unsigned target = (unsigned)t;
            unsigned long long p[8];
            for (;;) {
                bool ok = true;
#pragma unroll
                for (int j = 0; j < 4; j++) {
                    p[j] = ld_relaxed_u64(s0p + j);
                    ok &= ((unsigned)p[j] == target);
                }
#pragma unroll
                for (int j = 0; j < 4; j++) {
                    p[4 + j] = ld_relaxed_u64(s1p + j);
                    ok &= ((unsigned)p[4 + j] == target);
                }
                if (ok) break;
            }
            float4 v0, v1;
            v0.x = pub_val(p[0]); v0.y = pub_val(p[1]);
            v0.z = pub_val(p[2]); v0.w = pub_val(p[3]);
            v1.x = pub_val(p[4]); v1.y = pub_val(p[5]);
            v1.z = pub_val(p[6]); v1.w = pub_val(p[7]);
            a_sm4[tid]       = v0;
            a_sm4[tid + 256] = v1;
        } else {
            a_sm4[tid]       = make_float4(0.f, 0.f, 0.f, 0.f);
            a_sm4[tid + 256] = make_float4(0.f, 0.f, 0.f, 0.f);
        }
        __syncthreads();   // state staged

        // 2 rows x 2048 cols: 64 FFMA2 per lane, 4 independent chains
        unsigned long long acc0a = 0ull, acc0b = 0ull;
        unsigned long long acc1a = 0ull, acc1b = 0ull;
#pragma unroll
        for (int k = 0; k < 16; k++) {
            float4 av = a_sm4[k * 32 + lane];
            unsigned long long pa = packf2(av.x, av.y);
            unsigned long long pb = packf2(av.z, av.w);
            acc0a = ffma2(w0[k][0], pa, acc0a);
            acc0b = ffma2(w0[k][1], pb, acc0b);
            acc1a = ffma2(w1[k][0], pa, acc1a);
            acc1b = ffma2(w1[k][1], pb, acc1b);
        }
        float s0 = pair_sum(acc0a) + pair_sum(acc0b);
        float s1 = pair_sum(acc1a) + pair_sum(acc1b);

#pragma unroll
        for (int off = 16; off; off >>= 1) {
            s0 += __shfl_xor_sync(0xffffffffu, s0, off);
            s1 += __shfl_xor_sync(0xffffffffu, s1, off);
        }

        if (lane == 0) {
            float h0 = tanhf(s0 + xv.x);
            float h1 = tanhf(s1 + xv.y);
            float2 h; h.x = h0; h.y = h1;
            *(float2*)&out[(size_t)t * UNITS + row0] = h;
            unsigned long long* dst = g_pub[t & 1] + row0;
            st_relaxed_u64(dst,     make_pub(h0, (unsigned)(t + 1)));
            st_relaxed_u64(dst + 1, make_pub(h1, (unsigned)(t + 1)));
        }

        __syncthreads();   // a_sm safe to overwrite next step
    }
}

// ---------------------------------------------------------------------------
extern "C" void kernel_launch(void* const* d_in, const int* in_sizes, int n_in,
                              void* d_out, int out_size) {
    const float* x   = (const float*)d_in[0];   // (1, 8192, 512)
    const float* waa = (const float*)d_in[1];   // (2048, 2048)
    const float* wax = (const float*)d_in[2];   // (2048, 512)
    const float* ba  = (const float*)d_in[3];   // (2048, 1)
    float* out = (float*)d_out;                 // (1, 8192, 2048)

    dim3 grid(UNITS / 64, TSTEPS / 128);        // (32, 64)
    xin_gemm_kernel<<<grid, 256>>>(x, wax, ba); // also zeroes g_pub stamps

    scan_kernel<<<NCTA, SCAN_THREADS>>>(waa, out);
}